// round 6
// baseline (speedup 1.0000x reference)
#include <cuda_runtime.h>

// PotEnergy1P: out[b] = sum_{i<12,k} exp(-r)/(r+0.01), r = |x[b,i]-nbr[i,k]|
// Pipe-balanced: groups alternate between a MUFU-sqrt recipe (A) and an
// FMA-pipe rsqrt-Newton recipe (B) so MUFU and FMA pipes are both ~busy.
// ex2 stays MUFU (unavoidable); rcp via negative-magic seed + 2 Newton.
// All FMA math packed f32x2. Warp-uniform site split -> geometry LDS is a
// conflict-free broadcast. FAR padding self-masks through both paths.

#define NSITES 12
#define NMAX   64
#define NGRP   32          // 2-neighbor groups per site

typedef unsigned long long u64;
typedef unsigned int u32;

#define C_NEGLN2  0xBF317218BF317218ULL   // -ln(2)
#define C_NEGB    0xBC23D70ABC23D70AULL   // -0.01f
#define C_TWO     0x4000000040000000ULL   //  2.0f
#define C_NEG2    0xC0000000C0000000ULL   // -2.0f
#define C_NEGHALF 0xBF000000BF000000ULL   // -0.5f
#define C_1P5     0x3FC000003FC00000ULL   //  1.5f

__device__ __forceinline__ u64 pk2(float lo, float hi) {
    u64 r; asm("mov.b64 %0, {%1,%2};" : "=l"(r) : "f"(lo), "f"(hi)); return r;
}
__device__ __forceinline__ void upk2(float& lo, float& hi, u64 v) {
    asm("mov.b64 {%0,%1}, %2;" : "=f"(lo), "=f"(hi) : "l"(v));
}
__device__ __forceinline__ u64 addx2(u64 a, u64 b) {
    u64 d; asm("add.rn.f32x2 %0,%1,%2;" : "=l"(d) : "l"(a), "l"(b)); return d;
}
__device__ __forceinline__ u64 mulx2(u64 a, u64 b) {
    u64 d; asm("mul.rn.f32x2 %0,%1,%2;" : "=l"(d) : "l"(a), "l"(b)); return d;
}
__device__ __forceinline__ u64 fmx2(u64 a, u64 b, u64 c) {
    u64 d; asm("fma.rn.f32x2 %0,%1,%2,%3;" : "=l"(d) : "l"(a), "l"(b), "l"(c)); return d;
}
__device__ __forceinline__ float fsqrt_approx(float a) {
    float r; asm("sqrt.approx.f32 %0, %1;" : "=f"(r) : "f"(a)); return r;
}
// ex2(-a): negation folds into the MUFU source modifier.
__device__ __forceinline__ float fex2n(float a) {
    float r;
    asm("{.reg .f32 t; neg.f32 t, %1; ex2.approx.f32 %0, t;}"
        : "=f"(r) : "f"(a));
    return r;
}
// seed for -1/w given wn = -w (wn < 0): magic with u32 wraparound.
__device__ __forceinline__ float nseed(float a) {
    return __uint_as_float(0x7EF311C3u - __float_as_uint(a));
}
__device__ __forceinline__ u64 pkbits(float lo, float hi) {
    return (u64)__float_as_uint(lo) | ((u64)__float_as_uint(hi) << 32);
}

#define L2E 1.4426950408889634f

__global__ __launch_bounds__(256)
void pot_energy_kernel(const float* __restrict__ x,
                       const float* __restrict__ nbr,
                       const float* __restrict__ mask,
                       float* __restrict__ out,
                       int batch)
{
    // Geometry per 2-neighbor group, pre-negated and pre-scaled by log2(e).
    __shared__ ulonglong2 s_geo[NSITES * NGRP];
    __shared__ int        s_ngd[NSITES];
    __shared__ float      s_part[3][64];

    for (int j = threadIdx.x; j < NSITES * NGRP; j += blockDim.x) {
        int base = j * 4;
        float nx0 = nbr[base + 0], ny0 = nbr[base + 1];
        float nx1 = nbr[base + 2], ny1 = nbr[base + 3];
        ulonglong2 v;
        v.x = pkbits(-nx0 * L2E, -nx1 * L2E);
        v.y = pkbits(-ny0 * L2E, -ny1 * L2E);
        s_geo[j] = v;
    }
    if (threadIdx.x < NSITES) {
        int c = 0;
        for (int k = 0; k < NMAX; ++k)
            c += (mask[threadIdx.x * NMAX + k] > 0.5f) ? 1 : 0;
        int ng = (c + 1) >> 1;            // 2-pair groups (FAR tail self-masks)
        s_ngd[threadIdx.x] = (ng + 1) >> 1; // double-groups (A+B per iter)
    }
    __syncthreads();

    const int w    = threadIdx.x >> 5;          // 0..7
    const int half = w >> 2;
    const int sw   = w & 3;                     // sites 3sw..3sw+2
    const int lane = threadIdx.x & 31;
    const int hb   = half * 32 + lane;
    const int b    = blockIdx.x * 64 + hb;

    const float* xp = x + (size_t)b * 24 + sw * 6;
    float xs[6];
#pragma unroll
    for (int j = 0; j < 3; ++j) {
        float2 v = reinterpret_cast<const float2*>(xp)[j];
        xs[2 * j] = v.x * L2E; xs[2 * j + 1] = v.y * L2E;
    }

    u64 accA = 0ULL, accB = 0ULL;

#pragma unroll
    for (int s = 0; s < 3; ++s) {
        int site = 3 * sw + s;                  // warp-uniform
        u64 xip = pk2(xs[2 * s],     xs[2 * s]);
        u64 yip = pk2(xs[2 * s + 1], xs[2 * s + 1]);
        const ulonglong2* geo = s_geo + site * NGRP;
        int ngd = s_ngd[site];
#pragma unroll 2
        for (int kk = 0; kk < ngd; ++kk) {
            // ---- Group A: MUFU sqrt path ----
            {
                ulonglong2 q = geo[2 * kk];
                u64 dx = addx2(xip, q.x);
                u64 dy = addx2(yip, q.y);
                u64 d2 = fmx2(dx, dx, mulx2(dy, dy));
                float d2l, d2h; upk2(d2l, d2h, d2);
                float sl = fsqrt_approx(d2l);   // MUFU: s = r*log2(e)
                float sh = fsqrt_approx(d2h);   // MUFU
                float el = fex2n(sl);           // MUFU: exp(-r)
                float eh = fex2n(sh);           // MUFU
                u64 sp = pk2(sl, sh);
                u64 ep = pk2(el, eh);
                u64 wn = fmx2(sp, C_NEGLN2, C_NEGB);     // -(r+b)
                float wnl, wnh; upk2(wnl, wnh, wn);
                u64 yn = pk2(nseed(wnl), nseed(wnh));    // ~-(1/w)
                u64 t1 = fmx2(wn, yn, C_NEG2);
                u64 y1 = mulx2(yn, t1);
                u64 t2 = fmx2(wn, y1, C_TWO);
                u64 y2 = mulx2(y1, t2);                  // 1/(r+b)
                accA = fmx2(ep, y2, accA);
            }
            // ---- Group B: FMA-pipe rsqrt path ----
            {
                ulonglong2 q = geo[2 * kk + 1];
                u64 dx = addx2(xip, q.x);
                u64 dy = addx2(yip, q.y);
                u64 d2 = fmx2(dx, dx, mulx2(dy, dy));
                float d2l, d2h; upk2(d2l, d2h, d2);
                u32 sl32 = 0x5f3759dfu - (__float_as_uint(d2l) >> 1);
                u32 sh32 = 0x5f3759dfu - (__float_as_uint(d2h) >> 1);
                u64 y  = pk2(__uint_as_float(sl32), __uint_as_float(sh32));
                u64 hn = mulx2(d2, C_NEGHALF);           // -0.5*d2
                u64 yy = mulx2(y, y);
                u64 t  = fmx2(hn, yy, C_1P5);            // 1.5 - 0.5 d2 y^2
                y = mulx2(y, t);
                yy = mulx2(y, y);
                t  = fmx2(hn, yy, C_1P5);
                y = mulx2(y, t);                         // rsqrt(d2)
                u64 sp = mulx2(d2, y);                   // sqrt(d2) = r*log2(e)
                float sl, sh; upk2(sl, sh, sp);
                float el = fex2n(sl);                    // MUFU: exp(-r)
                float eh = fex2n(sh);                    // MUFU
                u64 ep = pk2(el, eh);
                u64 wn = fmx2(sp, C_NEGLN2, C_NEGB);     // -(r+b)
                float wnl, wnh; upk2(wnl, wnh, wn);
                u64 yn = pk2(nseed(wnl), nseed(wnh));
                u64 t1 = fmx2(wn, yn, C_NEG2);
                u64 y1 = mulx2(yn, t1);
                u64 t2 = fmx2(wn, y1, C_TWO);
                u64 y2 = mulx2(y1, t2);
                accB = fmx2(ep, y2, accB);
            }
        }
    }

    u64 acc = addx2(accA, accB);
    float al, ah; upk2(al, ah, acc);
    float v = al + ah;

    if (sw > 0) s_part[sw - 1][hb] = v;
    __syncthreads();
    if (sw == 0) {
        v += s_part[0][hb] + s_part[1][hb] + s_part[2][hb];
        out[b] = v;
    }
}

extern "C" void kernel_launch(void* const* d_in, const int* in_sizes, int n_in,
                              void* d_out, int out_size)
{
    const float* x    = (const float*)d_in[0];   // [B, 24]
    const float* nbr  = (const float*)d_in[1];   // [12, 64, 2]
    const float* mask = (const float*)d_in[2];   // [12, 64]
    float* out        = (float*)d_out;           // [B]

    int batch = in_sizes[0] / 24;                // 131072
    const int threads = 256;                     // 8 warps / 64 batch elems
    int blocks = batch / 64;                     // 2048
    pot_energy_kernel<<<blocks, threads>>>(x, nbr, mask, out, batch);
}

// round 7
// speedup vs baseline: 1.8065x; 1.8065x over previous
#include <cuda_runtime.h>

// PotEnergy1P: out[b] = sum_{i<12,k} exp(-r)/(r+0.01), r = |x[b,i]-nbr[i,k]|
// Round-5 recipe (2 MUFU/pair: sqrt + ex2; rcp via negative-magic seed +
// 2 Newton on FMA pipe; packed f32x2 math; geometry pre-scaled by log2(e))
// + 2 batch elements per thread: two independent dependency chains per warp
// to keep the MUFU pipe fed, sharing each geometry LDS between chains.

#define NSITES 12
#define NMAX   64
#define NGRP   32          // 2-neighbor groups per site

typedef unsigned long long u64;

#define C_NEGLN2 0xBF317218BF317218ULL   // -ln(2)
#define C_NEGB   0xBC23D70ABC23D70AULL   // -0.01f
#define C_TWO    0x4000000040000000ULL   //  2.0f
#define C_NEG2   0xC0000000C0000000ULL   // -2.0f

__device__ __forceinline__ u64 pk2(float lo, float hi) {
    u64 r; asm("mov.b64 %0, {%1,%2};" : "=l"(r) : "f"(lo), "f"(hi)); return r;
}
__device__ __forceinline__ void upk2(float& lo, float& hi, u64 v) {
    asm("mov.b64 {%0,%1}, %2;" : "=f"(lo), "=f"(hi) : "l"(v));
}
__device__ __forceinline__ u64 addx2(u64 a, u64 b) {
    u64 d; asm("add.rn.f32x2 %0,%1,%2;" : "=l"(d) : "l"(a), "l"(b)); return d;
}
__device__ __forceinline__ u64 mulx2(u64 a, u64 b) {
    u64 d; asm("mul.rn.f32x2 %0,%1,%2;" : "=l"(d) : "l"(a), "l"(b)); return d;
}
__device__ __forceinline__ u64 fmx2(u64 a, u64 b, u64 c) {
    u64 d; asm("fma.rn.f32x2 %0,%1,%2,%3;" : "=l"(d) : "l"(a), "l"(b), "l"(c)); return d;
}
__device__ __forceinline__ float fsqrt_approx(float a) {
    float r; asm("sqrt.approx.f32 %0, %1;" : "=f"(r) : "f"(a)); return r;
}
// ex2(-a): negation folds into the MUFU source modifier.
__device__ __forceinline__ float fex2n(float a) {
    float r;
    asm("{.reg .f32 t; neg.f32 t, %1; ex2.approx.f32 %0, t;}"
        : "=f"(r) : "f"(a));
    return r;
}
// seed for -1/w given wn = -w (wn < 0): magic with u32 wraparound.
__device__ __forceinline__ float nseed(float a) {
    return __uint_as_float(0x7EF311C3u - __float_as_uint(a));
}
__device__ __forceinline__ u64 pkbits(float lo, float hi) {
    return (u64)__float_as_uint(lo) | ((u64)__float_as_uint(hi) << 32);
}

#define L2E 1.4426950408889634f

__global__ __launch_bounds__(256, 5)
void pot_energy_kernel(const float* __restrict__ x,
                       const float* __restrict__ nbr,
                       const float* __restrict__ mask,
                       float* __restrict__ out,
                       int batch)
{
    // Geometry per 2-neighbor group, pre-negated and pre-scaled by log2(e).
    __shared__ ulonglong2 s_geo[NSITES * NGRP];
    __shared__ int        s_ng[NSITES];
    __shared__ float      s_part[3][128];

    for (int j = threadIdx.x; j < NSITES * NGRP; j += blockDim.x) {
        int base = j * 4;
        float nx0 = nbr[base + 0], ny0 = nbr[base + 1];
        float nx1 = nbr[base + 2], ny1 = nbr[base + 3];
        ulonglong2 v;
        v.x = pkbits(-nx0 * L2E, -nx1 * L2E);
        v.y = pkbits(-ny0 * L2E, -ny1 * L2E);
        s_geo[j] = v;
    }
    if (threadIdx.x < NSITES) {
        int c = 0;
        for (int k = 0; k < NMAX; ++k)
            c += (mask[threadIdx.x * NMAX + k] > 0.5f) ? 1 : 0;
        s_ng[threadIdx.x] = (c + 1) >> 1;       // odd tail self-masks (FAR)
    }
    __syncthreads();

    const int w    = threadIdx.x >> 5;          // 0..7
    const int half = w >> 2;                    // batch sub-chunk of 64
    const int sw   = w & 3;                     // sites 3sw..3sw+2
    const int lane = threadIdx.x & 31;
    const int hb0  = half * 64 + lane;          // elem A within block's 128
    const int hb1  = hb0 + 32;                  // elem B
    const int b0   = blockIdx.x * 128 + hb0;
    const int b1   = b0 + 32;

    // coords of this warp's 3 sites for both batch elems, pre-scaled by L2E
    const float* xp0 = x + (size_t)b0 * 24 + sw * 6;
    const float* xp1 = x + (size_t)b1 * 24 + sw * 6;
    float xs0[6], xs1[6];
#pragma unroll
    for (int j = 0; j < 3; ++j) {
        float2 v0 = reinterpret_cast<const float2*>(xp0)[j];
        float2 v1 = reinterpret_cast<const float2*>(xp1)[j];
        xs0[2 * j] = v0.x * L2E; xs0[2 * j + 1] = v0.y * L2E;
        xs1[2 * j] = v1.x * L2E; xs1[2 * j + 1] = v1.y * L2E;
    }

    u64 acc0 = 0ULL, acc1 = 0ULL;

#pragma unroll
    for (int s = 0; s < 3; ++s) {
        int site = 3 * sw + s;                  // warp-uniform
        u64 xip0 = pk2(xs0[2 * s],     xs0[2 * s]);
        u64 yip0 = pk2(xs0[2 * s + 1], xs0[2 * s + 1]);
        u64 xip1 = pk2(xs1[2 * s],     xs1[2 * s]);
        u64 yip1 = pk2(xs1[2 * s + 1], xs1[2 * s + 1]);
        const ulonglong2* geo = s_geo + site * NGRP;
        int ng = s_ng[site];
#pragma unroll 2
        for (int k = 0; k < ng; ++k) {
            ulonglong2 q = geo[k];              // LDS.128 broadcast, shared

            // chain 0
            u64 dxA = addx2(xip0, q.x);
            u64 dyA = addx2(yip0, q.y);
            u64 d2A = fmx2(dxA, dxA, mulx2(dyA, dyA));
            // chain 1
            u64 dxB = addx2(xip1, q.x);
            u64 dyB = addx2(yip1, q.y);
            u64 d2B = fmx2(dxB, dxB, mulx2(dyB, dyB));

            float dAl, dAh, dBl, dBh;
            upk2(dAl, dAh, d2A);
            upk2(dBl, dBh, d2B);
            float sAl = fsqrt_approx(dAl);      // MUFU: s = r*log2(e)
            float sAh = fsqrt_approx(dAh);
            float sBl = fsqrt_approx(dBl);
            float sBh = fsqrt_approx(dBh);
            float eAl = fex2n(sAl);             // MUFU: exp(-r) (FAR -> 0)
            float eAh = fex2n(sAh);
            float eBl = fex2n(sBl);
            float eBh = fex2n(sBh);

            u64 spA = pk2(sAl, sAh), epA = pk2(eAl, eAh);
            u64 spB = pk2(sBl, sBh), epB = pk2(eBl, eBh);

            u64 wnA = fmx2(spA, C_NEGLN2, C_NEGB);   // -(r+b)
            u64 wnB = fmx2(spB, C_NEGLN2, C_NEGB);
            float wAl, wAh, wBl, wBh;
            upk2(wAl, wAh, wnA);
            upk2(wBl, wBh, wnB);
            u64 ynA = pk2(nseed(wAl), nseed(wAh));   // ~ -(1/w)
            u64 ynB = pk2(nseed(wBl), nseed(wBh));

            u64 t1A = fmx2(wnA, ynA, C_NEG2);
            u64 t1B = fmx2(wnB, ynB, C_NEG2);
            u64 y1A = mulx2(ynA, t1A);
            u64 y1B = mulx2(ynB, t1B);
            u64 t2A = fmx2(wnA, y1A, C_TWO);
            u64 t2B = fmx2(wnB, y1B, C_TWO);
            u64 y2A = mulx2(y1A, t2A);               // 1/(r+b)
            u64 y2B = mulx2(y1B, t2B);

            acc0 = fmx2(epA, y2A, acc0);
            acc1 = fmx2(epB, y2B, acc1);
        }
    }

    float a0l, a0h, a1l, a1h;
    upk2(a0l, a0h, acc0);
    upk2(a1l, a1h, acc1);
    float v0 = a0l + a0h;
    float v1 = a1l + a1h;

    if (sw > 0) { s_part[sw - 1][hb0] = v0; s_part[sw - 1][hb1] = v1; }
    __syncthreads();
    if (sw == 0) {
        v0 += s_part[0][hb0] + s_part[1][hb0] + s_part[2][hb0];
        v1 += s_part[0][hb1] + s_part[1][hb1] + s_part[2][hb1];
        out[b0] = v0;
        out[b1] = v1;
    }
}

extern "C" void kernel_launch(void* const* d_in, const int* in_sizes, int n_in,
                              void* d_out, int out_size)
{
    const float* x    = (const float*)d_in[0];   // [B, 24]
    const float* nbr  = (const float*)d_in[1];   // [12, 64, 2]
    const float* mask = (const float*)d_in[2];   // [12, 64]
    float* out        = (float*)d_out;           // [B]

    int batch = in_sizes[0] / 24;                // 131072
    const int threads = 256;                     // 8 warps / 128 batch elems
    int blocks = batch / 128;                    // 1024
    pot_energy_kernel<<<blocks, threads>>>(x, nbr, mask, out, batch);
}